// round 14
// baseline (speedup 1.0000x reference)
#include <cuda_runtime.h>
#include <cuda_fp16.h>
#include <cstdint>

#define MAXN 65536
#define MAXE 2097152
#define EPSF 1e-5f
#define PADK 40   // halves per smem row per k-chunk (32 data + 8 pad)

// dynamic smem layout (bytes)
#define ABYTES  (64 * PADK * 2)            // 5120 per split
#define BBYTES  (256 * PADK * 2)           // 20480 per split
#define BUFB    (2 * ABYTES + 2 * BBYTES)  // 51200 per buffer
#define OFF_AH(b) ((b) * BUFB)
#define OFF_AL(b) ((b) * BUFB + ABYTES)
#define OFF_BH(b) ((b) * BUFB + 2 * ABYTES)
#define OFF_BL(b) ((b) * BUFB + 2 * ABYTES + BBYTES)
#define DSM_TOTAL (2 * BUFB + 1024)

// ================= scratch =================
__device__ uint2  g_Uh[MAXN * 32];    // act(X)@Wl, fp16
__device__ float4 g_V[MAXN * 32];     // act(X)@Wr, fp32
__device__ float4 g_H[MAXN * 32];     // pre-BN activations
__device__ float  g_stats[256];
__device__ float  g_scale[128];
__device__ float  g_shift[128];
__device__ int    g_is64;
__device__ int    g_cnt[MAXN];
__device__ int    g_rowptr[MAXN + 1];
__device__ int    g_colidx[MAXE];
__device__ int    g_btot[64];
__device__ int    g_boff[64];
__device__ __align__(16) __half g_BTh[4][32768];
__device__ __align__(16) __half g_BTl[4][32768];

__device__ __forceinline__ int edge_at(const void* ei, int which, int e, int E) {
    if (g_is64) return (int)((const long long*)ei)[(size_t)which * E + e];
    return ((const int*)ei)[(size_t)which * E + e];
}
__device__ __forceinline__ void add4(float4& a, const float4& b) {
    a.x += b.x; a.y += b.y; a.z += b.z; a.w += b.w;
}
__device__ __forceinline__ void addh4(float4& a, const uint2& u) {
    float2 lo = __half22float2(*reinterpret_cast<const __half2*>(&u.x));
    float2 hi = __half22float2(*reinterpret_cast<const __half2*>(&u.y));
    a.x += lo.x; a.y += lo.y; a.z += hi.x; a.w += hi.y;
}
__device__ __forceinline__ uint32_t smem_u32(const void* p) {
    uint32_t a;
    asm("{ .reg .u64 t; cvta.to.shared.u64 t, %1; cvt.u32.u64 %0, t; }" : "=r"(a) : "l"(p));
    return a;
}

#define CP_ASYNC16(dst, src) \
    asm volatile("cp.async.cg.shared.global [%0], [%1], 16;" :: "r"(dst), "l"(src))
#define CP_COMMIT() asm volatile("cp.async.commit_group;" ::: "memory")
#define CP_WAIT(n)  asm volatile("cp.async.wait_group %0;" :: "n"(n) : "memory")

#define LDSM4(R, addr)                                                      \
    asm volatile("ldmatrix.sync.aligned.m8n8.x4.shared.b16 {%0,%1,%2,%3}, [%4];" \
                 : "=r"((R)[0]), "=r"((R)[1]), "=r"((R)[2]), "=r"((R)[3])   \
                 : "r"(addr))

#define MMA16816(C, A, B0, B1)                                              \
    asm volatile("mma.sync.aligned.m16n8k16.row.col.f32.f16.f16.f32 "       \
                 "{%0,%1,%2,%3}, {%4,%5,%6,%7}, {%8,%9}, {%0,%1,%2,%3};"    \
                 : "+f"((C)[0]), "+f"((C)[1]), "+f"((C)[2]), "+f"((C)[3])   \
                 : "r"((A)[0]), "r"((A)[1]), "r"((A)[2]), "r"((A)[3]),      \
                   "r"(B0), "r"(B1))

// ================= dtype detect =================
__global__ void k_detect(const long long* __restrict__ ei, int N) {
    if (threadIdx.x == 0) {
        int ok = 1;
        for (int i = 0; i < 64; i++) {
            long long v = ei[i];
            if (v < 0 || v >= (long long)N) { ok = 0; break; }
        }
        g_is64 = ok;
    }
}

// ================= CSR build =================
__global__ void k_zero_cnt(int N) {
    int i = blockIdx.x * blockDim.x + threadIdx.x;
    if (i < N) g_cnt[i] = 0;
}
__global__ void k_hist(const void* __restrict__ ei, int E, int N) {
    int i = blockIdx.x * blockDim.x + threadIdx.x;
    if (i < E) {
        int d = edge_at(ei, 1, i, E);
        if ((unsigned)d < (unsigned)N) atomicAdd(&g_cnt[d], 1);
    }
}
__global__ __launch_bounds__(1024)
void k_scan1(int N) {
    __shared__ int wsum[32];
    int i = blockIdx.x * 1024 + threadIdx.x;
    int lane = threadIdx.x & 31, wid = threadIdx.x >> 5;
    int v = (i < N) ? g_cnt[i] : 0;
    int x = v;
#pragma unroll
    for (int o = 1; o < 32; o <<= 1) {
        int y = __shfl_up_sync(0xffffffffu, x, o);
        if (lane >= o) x += y;
    }
    if (lane == 31) wsum[wid] = x;
    __syncthreads();
    if (wid == 0) {
        int w = wsum[lane];
#pragma unroll
        for (int o = 1; o < 32; o <<= 1) {
            int y = __shfl_up_sync(0xffffffffu, w, o);
            if (lane >= o) w += y;
        }
        wsum[lane] = w;
    }
    __syncthreads();
    int incl = x + (wid > 0 ? wsum[wid - 1] : 0);
    if (i < N) g_rowptr[i + 1] = incl;
    if (threadIdx.x == 1023) g_btot[blockIdx.x] = incl;
}
__global__ void k_scan2(int nb) {
    __shared__ int w0tot;
    int lane = threadIdx.x & 31, wid = threadIdx.x >> 5;
    int v = (threadIdx.x < nb) ? g_btot[threadIdx.x] : 0;
    int x = v;
#pragma unroll
    for (int o = 1; o < 32; o <<= 1) {
        int y = __shfl_up_sync(0xffffffffu, x, o);
        if (lane >= o) x += y;
    }
    if (wid == 0 && lane == 31) w0tot = x;
    __syncthreads();
    int excl = x - v + (wid == 1 ? w0tot : 0);
    if (threadIdx.x < nb) g_boff[threadIdx.x] = excl;
    if (threadIdx.x == 0) g_rowptr[0] = 0;
}
__global__ __launch_bounds__(1024)
void k_scan3(int N) {
    int i = blockIdx.x * 1024 + threadIdx.x;
    if (i < N) g_rowptr[i + 1] += g_boff[blockIdx.x];
}
// destructive fill: rowptr[d] becomes original rowptr[d+1] after this kernel.
__global__ void k_fill(const void* __restrict__ ei, int E, int N) {
    int i = blockIdx.x * blockDim.x + threadIdx.x;
    if (i < E) {
        int s = edge_at(ei, 0, i, E);
        int d = edge_at(ei, 1, i, E);
        if ((unsigned)s >= (unsigned)N || (unsigned)d >= (unsigned)N) return;
        int pos = atomicAdd(&g_rowptr[d], 1);
        if (pos < MAXE) g_colidx[pos] = s;
    }
}

// ================= stats =================
__global__ void k_zero_stats() { g_stats[threadIdx.x] = 0.f; }
__global__ void k_finstats(const float* __restrict__ gamma,
                           const float* __restrict__ beta, float invN) {
    int c = threadIdx.x;
    float mu = g_stats[c] * invN;
    float var = g_stats[128 + c] * invN - mu * mu;
    float s = gamma[c] * rsqrtf(var + EPSF);
    g_scale[c] = s;
    g_shift[c] = beta[c] - mu * s;
    g_stats[c] = 0.f;
    g_stats[128 + c] = 0.f;
}

// ================= weight transpose + fp16 split (once) =================
__global__ void k_convW(const float* __restrict__ Wl, const float* __restrict__ Wr, int L) {
    int idx = blockIdx.x * blockDim.x + threadIdx.x;
    if (idx >= L * 32768) return;
    int l = idx >> 15;
    int r = idx & 32767;
    int n = r >> 7, k = r & 127;
    float v = (n < 128) ? Wl[(size_t)l * 16384 + k * 128 + n]
                        : Wr[(size_t)l * 16384 + k * 128 + (n - 128)];
    __half h = __float2half_rn(v);
    __half lo = __float2half_rn(v - __half2float(h));
    g_BTh[l][n * 128 + k] = h;
    g_BTl[l][n * 128 + k] = lo;
}

// ================= HMMA dual GEMM (cp.async, k-chunk 32, 4 iters) ===========
__global__ __launch_bounds__(256, 2)
void k_gemm(const float4* __restrict__ Xext, int applyBN, int layer, int Nn) {
    extern __shared__ __align__(16) unsigned char dsm[];
    const uint32_t sbase = smem_u32(dsm);
    float* s_sc = (float*)(dsm + 2 * BUFB);
    float* s_sh = s_sc + 128;

    const int tid = threadIdx.x;
    const int lane = tid & 31;
    const int wid = tid >> 5;
    const int warp_m = wid >> 2;      // 0..1
    const int warp_n = wid & 3;       // 0..3
    const int rowBase = blockIdx.x * 64;
    const float4* __restrict__ X = applyBN ? g_H : Xext;
    const uint4* __restrict__ BTh4 = (const uint4*)g_BTh[layer];
    const uint4* __restrict__ BTl4 = (const uint4*)g_BTl[layer];

    if (applyBN && tid < 128) { s_sc[tid] = g_scale[tid]; s_sh[tid] = g_shift[tid]; }
    __syncthreads();

    float acc[2][8][4];
#pragma unroll
    for (int mi = 0; mi < 2; mi++)
#pragma unroll
        for (int ni = 0; ni < 8; ni++)
#pragma unroll
            for (int j = 0; j < 4; j++) acc[mi][ni][j] = 0.f;

    // fragment base offsets (k-offset added per sub-step)
    const uint32_t aRow = (uint32_t)(warp_m * 32 + (lane & 15)) * PADK + (lane >> 4) * 8;
    const uint32_t bRow = (uint32_t)(warp_n * 64 + (lane & 7) + ((lane >> 4) << 3)) * PADK
                          + ((lane >> 3) & 1) * 8;

    // A staging: slots v = tid + t*256 -> row v>>3 (0..63), quad v&7 (0..7)
    const int aR0 = tid >> 3, aQ0 = tid & 7;
    const int aR1 = (tid + 256) >> 3, aQ1 = aQ0;   // same quad, row +32
    const bool inR0 = rowBase + aR0 < Nn;
    const bool inR1 = rowBase + aR1 < Nn;
    // B staging: row tid, 4 uint4 per split per chunk
    const uint32_t bDst = (uint32_t)tid * PADK * 2;

    // ---- prologue: cp.async B chunk0; prefetch A chunk0 ----
#pragma unroll
    for (int jj = 0; jj < 4; jj++) {
        CP_ASYNC16(sbase + OFF_BH(0) + bDst + jj * 16, BTh4 + tid * 16 + jj);
        CP_ASYNC16(sbase + OFF_BL(0) + bDst + jj * 16, BTl4 + tid * 16 + jj);
    }
    CP_COMMIT();
    float4 pA0 = make_float4(0.f, 0.f, 0.f, 0.f), pA1 = pA0;
    if (inR0) pA0 = X[(size_t)(rowBase + aR0) * 32 + aQ0];
    if (inR1) pA1 = X[(size_t)(rowBase + aR1) * 32 + aQ1];

#pragma unroll
    for (int kc = 0; kc < 4; kc++) {
        const int b = kc & 1;
        // ---- store A(kc): BN + fp16 split, both slots ----
#pragma unroll
        for (int t = 0; t < 2; t++) {
            float4 xv = t ? pA1 : pA0;
            int r = t ? aR1 : aR0;
            int q = t ? aQ1 : aQ0;
            if (applyBN) {
                int cb = (kc * 8 + q) * 4;
                xv.x = fmaxf(fmaf(xv.x, s_sc[cb + 0], s_sh[cb + 0]), 0.f);
                xv.y = fmaxf(fmaf(xv.y, s_sc[cb + 1], s_sh[cb + 1]), 0.f);
                xv.z = fmaxf(fmaf(xv.z, s_sc[cb + 2], s_sh[cb + 2]), 0.f);
                xv.w = fmaxf(fmaf(xv.w, s_sc[cb + 3], s_sh[cb + 3]), 0.f);
            }
            __half hx = __float2half_rn(xv.x), hy = __float2half_rn(xv.y);
            __half hz = __float2half_rn(xv.z), hw = __float2half_rn(xv.w);
            __half2 ph01 = __halves2half2(hx, hy);
            __half2 ph23 = __halves2half2(hz, hw);
            __half2 pl01 = __halves2half2(__float2half_rn(xv.x - __half2float(hx)),
                                          __float2half_rn(xv.y - __half2float(hy)));
            __half2 pl23 = __halves2half2(__float2half_rn(xv.z - __half2float(hz)),
                                          __float2half_rn(xv.w - __half2float(hw)));
            uint2 ph, pl;
            ph.x = *reinterpret_cast<unsigned*>(&ph01);
            ph.y = *reinterpret_cast<unsigned*>(&ph23);
            pl.x = *reinterpret_cast<unsigned*>(&pl01);
            pl.y = *reinterpret_cast<unsigned*>(&pl23);
            *(uint2*)(dsm + OFF_AH(b) + (r * PADK + q * 4) * 2) = ph;
            *(uint2*)(dsm + OFF_AL(b) + (r * PADK + q * 4) * 2) = pl;
        }
        // ---- issue next chunk ----
        if (kc < 3) {
            const int kn = kc + 1;
            const int nb2 = 1 - b;
#pragma unroll
            for (int jj = 0; jj < 4; jj++) {
                CP_ASYNC16(sbase + OFF_BH(nb2) + bDst + jj * 16, BTh4 + tid * 16 + kn * 4 + jj);
                CP_ASYNC16(sbase + OFF_BL(nb2) + bDst + jj * 16, BTl4 + tid * 16 + kn * 4 + jj);
            }
            CP_COMMIT();
            if (inR0) pA0 = X[(size_t)(rowBase + aR0) * 32 + kn * 8 + aQ0];
            if (inR1) pA1 = X[(size_t)(rowBase + aR1) * 32 + kn * 8 + aQ1];
            CP_WAIT(1);
        } else {
            CP_WAIT(0);
        }
        __syncthreads();

        // ---- compute from buf b: two k16 sub-steps ----
        const uint32_t aShB = sbase + OFF_AH(b), aSlB = sbase + OFF_AL(b);
        const uint32_t bShB = sbase + OFF_BH(b), bSlB = sbase + OFF_BL(b);
#pragma unroll
        for (int ks = 0; ks < 2; ks++) {
            const uint32_t aOff = (aRow + ks * 16) * 2;
            const uint32_t bOff = (bRow + ks * 16) * 2;
            uint32_t ah[2][4], al[2][4], bb[8][2];
#pragma unroll
            for (int mi = 0; mi < 2; mi++) {
                LDSM4(ah[mi], aShB + aOff + mi * (16 * PADK * 2));
                LDSM4(al[mi], aSlB + aOff + mi * (16 * PADK * 2));
            }
#pragma unroll
            for (int p = 0; p < 4; p++) {
                uint32_t t4[4];
                LDSM4(t4, bShB + bOff + p * (16 * PADK * 2));
                bb[2 * p][0] = t4[0]; bb[2 * p][1] = t4[1];
                bb[2 * p + 1][0] = t4[2]; bb[2 * p + 1][1] = t4[3];
            }
#pragma unroll
            for (int mi = 0; mi < 2; mi++)
#pragma unroll
                for (int ni = 0; ni < 8; ni++) {
                    MMA16816(acc[mi][ni], ah[mi], bb[ni][0], bb[ni][1]);
                    MMA16816(acc[mi][ni], al[mi], bb[ni][0], bb[ni][1]);
                }
#pragma unroll
            for (int p = 0; p < 4; p++) {
                uint32_t t4[4];
                LDSM4(t4, bSlB + bOff + p * (16 * PADK * 2));
                bb[2 * p][0] = t4[0]; bb[2 * p][1] = t4[1];
                bb[2 * p + 1][0] = t4[2]; bb[2 * p + 1][1] = t4[3];
            }
#pragma unroll
            for (int mi = 0; mi < 2; mi++)
#pragma unroll
                for (int ni = 0; ni < 8; ni++)
                    MMA16816(acc[mi][ni], ah[mi], bb[ni][0], bb[ni][1]);
        }
        __syncthreads();
    }

    // ---- epilogue ----
    __half* Uh = (__half*)g_Uh;
    float* Vf = (float*)g_V;
#pragma unroll
    for (int mi = 0; mi < 2; mi++) {
        int r0 = rowBase + warp_m * 32 + mi * 16 + (lane >> 2);
        int r1 = r0 + 8;
#pragma unroll
        for (int ni = 0; ni < 8; ni++) {
            int col = warp_n * 64 + ni * 8 + (lane & 3) * 2;
            float c0 = acc[mi][ni][0], c1 = acc[mi][ni][1];
            float c2 = acc[mi][ni][2], c3 = acc[mi][ni][3];
            if (col < 128) {
                if (r0 < Nn)
                    *(__half2*)(Uh + (size_t)r0 * 128 + col) = __floats2half2_rn(c0, c1);
                if (r1 < Nn)
                    *(__half2*)(Uh + (size_t)r1 * 128 + col) = __floats2half2_rn(c2, c3);
            } else {
                int cv = col - 128;
                if (r0 < Nn)
                    *(float2*)(Vf + (size_t)r0 * 128 + cv) = make_float2(c0, c1);
                if (r1 < Nn)
                    *(float2*)(Vf + (size_t)r1 * 128 + cv) = make_float2(c2, c3);
            }
        }
    }
}

// ================= gather-mean (fp16 U) + bias + BN stats =================
// NOTE: rowptr is shifted by k_fill: row d spans [rowptr[d-1], rowptr[d]) (row 0 from 0).
__global__ __launch_bounds__(256)
void k_aggr(const float4* __restrict__ b4, int N) {
    __shared__ float sS[256];
    if (threadIdx.x < 256) sS[threadIdx.x] = 0.f;
    __syncthreads();

    const int lane = threadIdx.x & 31;
    const int gwarp = blockIdx.x * (blockDim.x >> 5) + (threadIdx.x >> 5);
    const int nWarps = gridDim.x * (blockDim.x >> 5);

    const float4 z4 = make_float4(0.f, 0.f, 0.f, 0.f);
    float4 wSum = z4, wSq = z4;
    const float4 bv = b4[lane];

    for (int node = gwarp; node < N; node += nWarps) {
        int beg = (node == 0) ? 0 : g_rowptr[node - 1];
        int end = g_rowptr[node];
        float4 acc0 = z4, acc1 = z4;
        int e = beg;
        for (; e + 1 < end; e += 2) {
            int s0 = g_colidx[e];
            int s1 = g_colidx[e + 1];
            uint2 u0 = g_Uh[(size_t)s0 * 32 + lane];
            uint2 u1 = g_Uh[(size_t)s1 * 32 + lane];
            addh4(acc0, u0);
            addh4(acc1, u1);
        }
        if (e < end) addh4(acc0, g_Uh[(size_t)g_colidx[e] * 32 + lane]);
        add4(acc0, acc1);

        float di = 1.0f / fmaxf((float)(end - beg), 1.0f);
        float4 v = g_V[(size_t)node * 32 + lane];
        float4 h;
        h.x = fmaf(acc0.x, di, v.x) + bv.x;
        h.y = fmaf(acc0.y, di, v.y) + bv.y;
        h.z = fmaf(acc0.z, di, v.z) + bv.z;
        h.w = fmaf(acc0.w, di, v.w) + bv.w;
        g_H[(size_t)node * 32 + lane] = h;

        add4(wSum, h);
        wSq.x = fmaf(h.x, h.x, wSq.x);
        wSq.y = fmaf(h.y, h.y, wSq.y);
        wSq.z = fmaf(h.z, h.z, wSq.z);
        wSq.w = fmaf(h.w, h.w, wSq.w);
    }

    int c = lane * 4;
    atomicAdd(&sS[c + 0], wSum.x);
    atomicAdd(&sS[c + 1], wSum.y);
    atomicAdd(&sS[c + 2], wSum.z);
    atomicAdd(&sS[c + 3], wSum.w);
    atomicAdd(&sS[128 + c + 0], wSq.x);
    atomicAdd(&sS[128 + c + 1], wSq.y);
    atomicAdd(&sS[128 + c + 2], wSq.z);
    atomicAdd(&sS[128 + c + 3], wSq.w);
    __syncthreads();
    if (threadIdx.x < 256) atomicAdd(&g_stats[threadIdx.x], sS[threadIdx.x]);
}

// ================= final BN + ReLU =================
__global__ void k_epi2(float4* __restrict__ out, int N) {
    __shared__ float sc[128], sh[128];
    if (threadIdx.x < 128) {
        sc[threadIdx.x] = g_scale[threadIdx.x];
        sh[threadIdx.x] = g_shift[threadIdx.x];
    }
    __syncthreads();
    int n4 = N * 32;
    for (int i = blockIdx.x * blockDim.x + threadIdx.x; i < n4;
         i += gridDim.x * blockDim.x) {
        int cq = (i & 31) * 4;
        float4 h = g_H[i];
        float4 o;
        o.x = fmaxf(fmaf(h.x, sc[cq + 0], sh[cq + 0]), 0.f);
        o.y = fmaxf(fmaf(h.y, sc[cq + 1], sh[cq + 1]), 0.f);
        o.z = fmaxf(fmaf(h.z, sc[cq + 2], sh[cq + 2]), 0.f);
        o.w = fmaxf(fmaf(h.w, sc[cq + 3], sh[cq + 3]), 0.f);
        out[i] = o;
    }
}

// ================= launch =================
extern "C" void kernel_launch(void* const* d_in, const int* in_sizes, int n_in,
                              void* d_out, int out_size) {
    const float4* x = (const float4*)d_in[0];
    const void* ei = d_in[1];
    const float* Wl = (const float*)d_in[2];
    const float* Wr = (const float*)d_in[3];
    const float* b = (const float*)d_in[4];
    const float* gamma = (const float*)d_in[5];
    const float* beta = (const float*)d_in[6];

    int N = in_sizes[0] / 128;
    int E = in_sizes[1] / 2;
    int L = in_sizes[4] / 128;
    if (L > 4) L = 4;
    float4* out = (float4*)d_out;
    float invN = 1.0f / (float)N;

    cudaFuncSetAttribute(k_gemm, cudaFuncAttributeMaxDynamicSharedMemorySize, DSM_TOTAL);

    int eb = (E + 255) / 256;
    int nb = (N + 255) / 256;
    int nb1 = (N + 1023) / 1024;

    k_detect<<<1, 32>>>((const long long*)ei, N);
    k_zero_cnt<<<nb, 256>>>(N);
    k_hist<<<eb, 256>>>(ei, E, N);
    k_scan1<<<nb1, 1024>>>(N);
    k_scan2<<<1, 64>>>(nb1);
    k_scan3<<<nb1, 1024>>>(N);
    k_fill<<<eb, 256>>>(ei, E, N);
    k_zero_stats<<<1, 256>>>();
    k_convW<<<(L * 32768 + 255) / 256, 256>>>(Wl, Wr, L);

    int gemmBlocks = (N + 63) / 64;
    for (int l = 0; l < L; l++) {
        k_gemm<<<gemmBlocks, 256, DSM_TOTAL>>>(x, (l == 0) ? 0 : 1, l, N);
        k_aggr<<<1184, 256>>>((const float4*)b + (size_t)l * 32, N);
        k_finstats<<<1, 128>>>(gamma + (size_t)l * 128, beta + (size_t)l * 128, invN);
    }
    k_epi2<<<1184, 256>>>(out, N);
}

// round 15
// speedup vs baseline: 1.1005x; 1.1005x over previous
#include <cuda_runtime.h>
#include <cuda_fp16.h>
#include <cstdint>

#define MAXN 65536
#define MAXE 2097152
#define EPSF 1e-5f
#define PADK 24   // halves per smem row per k-chunk (16 data + 8 pad)

// dynamic smem layout (bytes)
#define ABYTES  (64 * PADK * 2)            // 3072 per split
#define BBYTES  (256 * PADK * 2)           // 12288 per split
#define BUFB    (2 * ABYTES + 2 * BBYTES)  // 30720 per buffer
#define OFF_AH(b) ((b) * BUFB)
#define OFF_AL(b) ((b) * BUFB + ABYTES)
#define OFF_BH(b) ((b) * BUFB + 2 * ABYTES)
#define OFF_BL(b) ((b) * BUFB + 2 * ABYTES + BBYTES)
#define DSM_TOTAL (2 * BUFB + 1024)        // 62464: 2 CTAs/SM fit comfortably

// ================= scratch =================
__device__ uint2  g_Uh[MAXN * 32];    // act(X)@Wl, fp16
__device__ float4 g_V[MAXN * 32];     // act(X)@Wr, fp32
__device__ float4 g_H[MAXN * 32];     // pre-BN activations
__device__ float  g_stats[256];
__device__ float  g_scale[128];
__device__ float  g_shift[128];
__device__ int    g_is64;
__device__ int    g_cnt[MAXN];
__device__ int    g_rowptr[MAXN + 1];
__device__ int    g_colidx[MAXE];
__device__ int    g_btot[64];
__device__ int    g_boff[64];
__device__ __align__(16) __half g_BTh[4][32768];
__device__ __align__(16) __half g_BTl[4][32768];

__device__ __forceinline__ int edge_at(const void* ei, int which, int e, int E) {
    if (g_is64) return (int)((const long long*)ei)[(size_t)which * E + e];
    return ((const int*)ei)[(size_t)which * E + e];
}
__device__ __forceinline__ void add4(float4& a, const float4& b) {
    a.x += b.x; a.y += b.y; a.z += b.z; a.w += b.w;
}
__device__ __forceinline__ void addh4(float4& a, const uint2& u) {
    float2 lo = __half22float2(*reinterpret_cast<const __half2*>(&u.x));
    float2 hi = __half22float2(*reinterpret_cast<const __half2*>(&u.y));
    a.x += lo.x; a.y += lo.y; a.z += hi.x; a.w += hi.y;
}
__device__ __forceinline__ uint32_t smem_u32(const void* p) {
    uint32_t a;
    asm("{ .reg .u64 t; cvta.to.shared.u64 t, %1; cvt.u32.u64 %0, t; }" : "=r"(a) : "l"(p));
    return a;
}

#define CP_ASYNC16(dst, src) \
    asm volatile("cp.async.cg.shared.global [%0], [%1], 16;" :: "r"(dst), "l"(src))
#define CP_COMMIT() asm volatile("cp.async.commit_group;" ::: "memory")
#define CP_WAIT(n)  asm volatile("cp.async.wait_group %0;" :: "n"(n) : "memory")

#define LDSM4(R, addr)                                                      \
    asm volatile("ldmatrix.sync.aligned.m8n8.x4.shared.b16 {%0,%1,%2,%3}, [%4];" \
                 : "=r"((R)[0]), "=r"((R)[1]), "=r"((R)[2]), "=r"((R)[3])   \
                 : "r"(addr))

#define MMA16816(C, A, B0, B1)                                              \
    asm volatile("mma.sync.aligned.m16n8k16.row.col.f32.f16.f16.f32 "       \
                 "{%0,%1,%2,%3}, {%4,%5,%6,%7}, {%8,%9}, {%0,%1,%2,%3};"    \
                 : "+f"((C)[0]), "+f"((C)[1]), "+f"((C)[2]), "+f"((C)[3])   \
                 : "r"((A)[0]), "r"((A)[1]), "r"((A)[2]), "r"((A)[3]),      \
                   "r"(B0), "r"(B1))

// ================= dtype detect =================
__global__ void k_detect(const long long* __restrict__ ei, int N) {
    if (threadIdx.x == 0) {
        int ok = 1;
        for (int i = 0; i < 64; i++) {
            long long v = ei[i];
            if (v < 0 || v >= (long long)N) { ok = 0; break; }
        }
        g_is64 = ok;
    }
}

// ================= CSR build =================
__global__ void k_zero_cnt(int N) {
    int i = blockIdx.x * blockDim.x + threadIdx.x;
    if (i < N) g_cnt[i] = 0;
}
__global__ void k_hist(const void* __restrict__ ei, int E, int N) {
    int i = blockIdx.x * blockDim.x + threadIdx.x;
    if (i < E) {
        int d = edge_at(ei, 1, i, E);
        if ((unsigned)d < (unsigned)N) atomicAdd(&g_cnt[d], 1);
    }
}
__global__ __launch_bounds__(1024)
void k_scan1(int N) {
    __shared__ int wsum[32];
    int i = blockIdx.x * 1024 + threadIdx.x;
    int lane = threadIdx.x & 31, wid = threadIdx.x >> 5;
    int v = (i < N) ? g_cnt[i] : 0;
    int x = v;
#pragma unroll
    for (int o = 1; o < 32; o <<= 1) {
        int y = __shfl_up_sync(0xffffffffu, x, o);
        if (lane >= o) x += y;
    }
    if (lane == 31) wsum[wid] = x;
    __syncthreads();
    if (wid == 0) {
        int w = wsum[lane];
#pragma unroll
        for (int o = 1; o < 32; o <<= 1) {
            int y = __shfl_up_sync(0xffffffffu, w, o);
            if (lane >= o) w += y;
        }
        wsum[lane] = w;
    }
    __syncthreads();
    int incl = x + (wid > 0 ? wsum[wid - 1] : 0);
    if (i < N) g_rowptr[i + 1] = incl;
    if (threadIdx.x == 1023) g_btot[blockIdx.x] = incl;
}
__global__ void k_scan2(int nb) {
    __shared__ int w0tot;
    int lane = threadIdx.x & 31, wid = threadIdx.x >> 5;
    int v = (threadIdx.x < nb) ? g_btot[threadIdx.x] : 0;
    int x = v;
#pragma unroll
    for (int o = 1; o < 32; o <<= 1) {
        int y = __shfl_up_sync(0xffffffffu, x, o);
        if (lane >= o) x += y;
    }
    if (wid == 0 && lane == 31) w0tot = x;
    __syncthreads();
    int excl = x - v + (wid == 1 ? w0tot : 0);
    if (threadIdx.x < nb) g_boff[threadIdx.x] = excl;
    if (threadIdx.x == 0) g_rowptr[0] = 0;
}
__global__ __launch_bounds__(1024)
void k_scan3(int N) {
    int i = blockIdx.x * 1024 + threadIdx.x;
    if (i < N) g_rowptr[i + 1] += g_boff[blockIdx.x];
}
// destructive fill: rowptr[d] becomes original rowptr[d+1] after this kernel.
__global__ void k_fill(const void* __restrict__ ei, int E, int N) {
    int i = blockIdx.x * blockDim.x + threadIdx.x;
    if (i < E) {
        int s = edge_at(ei, 0, i, E);
        int d = edge_at(ei, 1, i, E);
        if ((unsigned)s >= (unsigned)N || (unsigned)d >= (unsigned)N) return;
        int pos = atomicAdd(&g_rowptr[d], 1);
        if (pos < MAXE) g_colidx[pos] = s;
    }
}

// ================= stats =================
__global__ void k_zero_stats() { g_stats[threadIdx.x] = 0.f; }
__global__ void k_finstats(const float* __restrict__ gamma,
                           const float* __restrict__ beta, float invN) {
    int c = threadIdx.x;
    float mu = g_stats[c] * invN;
    float var = g_stats[128 + c] * invN - mu * mu;
    float s = gamma[c] * rsqrtf(var + EPSF);
    g_scale[c] = s;
    g_shift[c] = beta[c] - mu * s;
    g_stats[c] = 0.f;
    g_stats[128 + c] = 0.f;
}

// ================= weight transpose + fp16 split (once) =================
__global__ void k_convW(const float* __restrict__ Wl, const float* __restrict__ Wr, int L) {
    int idx = blockIdx.x * blockDim.x + threadIdx.x;
    if (idx >= L * 32768) return;
    int l = idx >> 15;
    int r = idx & 32767;
    int n = r >> 7, k = r & 127;
    float v = (n < 128) ? Wl[(size_t)l * 16384 + k * 128 + n]
                        : Wr[(size_t)l * 16384 + k * 128 + (n - 128)];
    __half h = __float2half_rn(v);
    __half lo = __float2half_rn(v - __half2float(h));
    g_BTh[l][n * 128 + k] = h;
    g_BTl[l][n * 128 + k] = lo;
}

// ================= HMMA dual GEMM (cp.async double-buffered B, k-chunk 16) ====
__global__ __launch_bounds__(256, 2)
void k_gemm(const float4* __restrict__ Xext, int applyBN, int layer, int Nn) {
    extern __shared__ __align__(16) unsigned char dsm[];
    const uint32_t sbase = smem_u32(dsm);
    float* s_sc = (float*)(dsm + 2 * BUFB);
    float* s_sh = s_sc + 128;

    const int tid = threadIdx.x;
    const int lane = tid & 31;
    const int wid = tid >> 5;
    const int warp_m = wid >> 2;      // 0..1
    const int warp_n = wid & 3;       // 0..3
    const int rowBase = blockIdx.x * 64;
    const float4* __restrict__ X = applyBN ? g_H : Xext;
    const uint4* __restrict__ BTh4 = (const uint4*)g_BTh[layer];
    const uint4* __restrict__ BTl4 = (const uint4*)g_BTl[layer];

    if (applyBN && tid < 128) { s_sc[tid] = g_scale[tid]; s_sh[tid] = g_shift[tid]; }
    __syncthreads();

    float acc[2][8][4];
#pragma unroll
    for (int mi = 0; mi < 2; mi++)
#pragma unroll
        for (int ni = 0; ni < 8; ni++)
#pragma unroll
            for (int j = 0; j < 4; j++) acc[mi][ni][j] = 0.f;

    const uint32_t aOff = ((warp_m * 32 + (lane & 15)) * PADK + (lane >> 4) * 8) * 2;
    const uint32_t bOff = ((warp_n * 64 + (lane & 7) + ((lane >> 4) << 3)) * PADK
                          + ((lane >> 3) & 1) * 8) * 2;

    const int stR = tid >> 2, stQ = tid & 3;   // A staging: row 0..63, float4-quad 0..3
    const int stGrow = rowBase + stR;
    const bool inRange = stGrow < Nn;
    const int bn0 = tid >> 1, bjj = tid & 1;   // B staging slots
    const uint32_t bDst0 = (uint32_t)(bn0 * PADK + bjj * 8) * 2;
    const uint32_t bDst1 = (uint32_t)((bn0 + 128) * PADK + bjj * 8) * 2;

    // ---- prologue: cp.async B chunk0 -> buf0; prefetch A chunk0 -> regs ----
    CP_ASYNC16(sbase + OFF_BH(0) + bDst0, BTh4 + bn0 * 16 + bjj);
    CP_ASYNC16(sbase + OFF_BH(0) + bDst1, BTh4 + (bn0 + 128) * 16 + bjj);
    CP_ASYNC16(sbase + OFF_BL(0) + bDst0, BTl4 + bn0 * 16 + bjj);
    CP_ASYNC16(sbase + OFF_BL(0) + bDst1, BTl4 + (bn0 + 128) * 16 + bjj);
    CP_COMMIT();
    float4 pA = make_float4(0.f, 0.f, 0.f, 0.f);
    if (inRange) pA = X[(size_t)stGrow * 32 + stQ];

#pragma unroll
    for (int kc = 0; kc < 8; kc++) {
        const int b = kc & 1;
        // ---- store A(kc) (BN + fp16 split) into buf b ----
        {
            float4 xv = pA;
            if (applyBN) {
                int cb = (kc * 4 + stQ) * 4;
                xv.x = fmaxf(fmaf(xv.x, s_sc[cb + 0], s_sh[cb + 0]), 0.f);
                xv.y = fmaxf(fmaf(xv.y, s_sc[cb + 1], s_sh[cb + 1]), 0.f);
                xv.z = fmaxf(fmaf(xv.z, s_sc[cb + 2], s_sh[cb + 2]), 0.f);
                xv.w = fmaxf(fmaf(xv.w, s_sc[cb + 3], s_sh[cb + 3]), 0.f);
            }
            __half hx = __float2half_rn(xv.x), hy = __float2half_rn(xv.y);
            __half hz = __float2half_rn(xv.z), hw = __float2half_rn(xv.w);
            __half2 ph01 = __halves2half2(hx, hy);
            __half2 ph23 = __halves2half2(hz, hw);
            __half2 pl01 = __halves2half2(__float2half_rn(xv.x - __half2float(hx)),
                                          __float2half_rn(xv.y - __half2float(hy)));
            __half2 pl23 = __halves2half2(__float2half_rn(xv.z - __half2float(hz)),
                                          __float2half_rn(xv.w - __half2float(hw)));
            uint2 ph, pl;
            ph.x = *reinterpret_cast<unsigned*>(&ph01);
            ph.y = *reinterpret_cast<unsigned*>(&ph23);
            pl.x = *reinterpret_cast<unsigned*>(&pl01);
            pl.y = *reinterpret_cast<unsigned*>(&pl23);
            *(uint2*)(dsm + OFF_AH(b) + (stR * PADK + stQ * 4) * 2) = ph;
            *(uint2*)(dsm + OFF_AL(b) + (stR * PADK + stQ * 4) * 2) = pl;
        }
        // ---- issue next chunk: B via cp.async into buf 1-b, A into regs ----
        if (kc < 7) {
            const int kn = kc + 1;
            const int nb2 = 1 - b;
            CP_ASYNC16(sbase + OFF_BH(nb2) + bDst0, BTh4 + bn0 * 16 + kn * 2 + bjj);
            CP_ASYNC16(sbase + OFF_BH(nb2) + bDst1, BTh4 + (bn0 + 128) * 16 + kn * 2 + bjj);
            CP_ASYNC16(sbase + OFF_BL(nb2) + bDst0, BTl4 + bn0 * 16 + kn * 2 + bjj);
            CP_ASYNC16(sbase + OFF_BL(nb2) + bDst1, BTl4 + (bn0 + 128) * 16 + kn * 2 + bjj);
            CP_COMMIT();
            if (inRange) pA = X[(size_t)stGrow * 32 + kn * 4 + stQ];
            CP_WAIT(1);
        } else {
            CP_WAIT(0);
        }
        __syncthreads();

        // ---- compute from buf b ----
        const uint32_t aShB = sbase + OFF_AH(b), aSlB = sbase + OFF_AL(b);
        const uint32_t bShB = sbase + OFF_BH(b), bSlB = sbase + OFF_BL(b);
        uint32_t ah[2][4], al[2][4], bb[8][2];
#pragma unroll
        for (int mi = 0; mi < 2; mi++) {
            LDSM4(ah[mi], aShB + aOff + mi * (16 * PADK * 2));
            LDSM4(al[mi], aSlB + aOff + mi * (16 * PADK * 2));
        }
#pragma unroll
        for (int p = 0; p < 4; p++) {
            uint32_t t4[4];
            LDSM4(t4, bShB + bOff + p * (16 * PADK * 2));
            bb[2 * p][0] = t4[0]; bb[2 * p][1] = t4[1];
            bb[2 * p + 1][0] = t4[2]; bb[2 * p + 1][1] = t4[3];
        }
#pragma unroll
        for (int mi = 0; mi < 2; mi++)
#pragma unroll
            for (int ni = 0; ni < 8; ni++) {
                MMA16816(acc[mi][ni], ah[mi], bb[ni][0], bb[ni][1]);
                MMA16816(acc[mi][ni], al[mi], bb[ni][0], bb[ni][1]);
            }
#pragma unroll
        for (int p = 0; p < 4; p++) {
            uint32_t t4[4];
            LDSM4(t4, bSlB + bOff + p * (16 * PADK * 2));
            bb[2 * p][0] = t4[0]; bb[2 * p][1] = t4[1];
            bb[2 * p + 1][0] = t4[2]; bb[2 * p + 1][1] = t4[3];
        }
#pragma unroll
        for (int mi = 0; mi < 2; mi++)
#pragma unroll
            for (int ni = 0; ni < 8; ni++)
                MMA16816(acc[mi][ni], ah[mi], bb[ni][0], bb[ni][1]);
        __syncthreads();
    }

    // ---- epilogue ----
    __half* Uh = (__half*)g_Uh;
    float* Vf = (float*)g_V;
#pragma unroll
    for (int mi = 0; mi < 2; mi++) {
        int r0 = rowBase + warp_m * 32 + mi * 16 + (lane >> 2);
        int r1 = r0 + 8;
#pragma unroll
        for (int ni = 0; ni < 8; ni++) {
            int col = warp_n * 64 + ni * 8 + (lane & 3) * 2;
            float c0 = acc[mi][ni][0], c1 = acc[mi][ni][1];
            float c2 = acc[mi][ni][2], c3 = acc[mi][ni][3];
            if (col < 128) {
                if (r0 < Nn)
                    *(__half2*)(Uh + (size_t)r0 * 128 + col) = __floats2half2_rn(c0, c1);
                if (r1 < Nn)
                    *(__half2*)(Uh + (size_t)r1 * 128 + col) = __floats2half2_rn(c2, c3);
            } else {
                int cv = col - 128;
                if (r0 < Nn)
                    *(float2*)(Vf + (size_t)r0 * 128 + cv) = make_float2(c0, c1);
                if (r1 < Nn)
                    *(float2*)(Vf + (size_t)r1 * 128 + cv) = make_float2(c2, c3);
            }
        }
    }
}

// ================= gather-mean (fp16 U) + bias + BN stats =================
// NOTE: rowptr is shifted by k_fill: row d spans [rowptr[d-1], rowptr[d]) (row 0 from 0).
__global__ __launch_bounds__(256)
void k_aggr(const float4* __restrict__ b4, int N) {
    __shared__ float sS[256];
    if (threadIdx.x < 256) sS[threadIdx.x] = 0.f;
    __syncthreads();

    const int lane = threadIdx.x & 31;
    const int gwarp = blockIdx.x * (blockDim.x >> 5) + (threadIdx.x >> 5);
    const int nWarps = gridDim.x * (blockDim.x >> 5);

    const float4 z4 = make_float4(0.f, 0.f, 0.f, 0.f);
    float4 wSum = z4, wSq = z4;
    const float4 bv = b4[lane];

    for (int node = gwarp; node < N; node += nWarps) {
        int beg = (node == 0) ? 0 : g_rowptr[node - 1];
        int end = g_rowptr[node];
        float4 acc0 = z4, acc1 = z4;
        int e = beg;
        for (; e + 1 < end; e += 2) {
            int s0 = g_colidx[e];
            int s1 = g_colidx[e + 1];
            uint2 u0 = g_Uh[(size_t)s0 * 32 + lane];
            uint2 u1 = g_Uh[(size_t)s1 * 32 + lane];
            addh4(acc0, u0);
            addh4(acc1, u1);
        }
        if (e < end) addh4(acc0, g_Uh[(size_t)g_colidx[e] * 32 + lane]);
        add4(acc0, acc1);

        float di = 1.0f / fmaxf((float)(end - beg), 1.0f);
        float4 v = g_V[(size_t)node * 32 + lane];
        float4 h;
        h.x = fmaf(acc0.x, di, v.x) + bv.x;
        h.y = fmaf(acc0.y, di, v.y) + bv.y;
        h.z = fmaf(acc0.z, di, v.z) + bv.z;
        h.w = fmaf(acc0.w, di, v.w) + bv.w;
        g_H[(size_t)node * 32 + lane] = h;

        add4(wSum, h);
        wSq.x = fmaf(h.x, h.x, wSq.x);
        wSq.y = fmaf(h.y, h.y, wSq.y);
        wSq.z = fmaf(h.z, h.z, wSq.z);
        wSq.w = fmaf(h.w, h.w, wSq.w);
    }

    int c = lane * 4;
    atomicAdd(&sS[c + 0], wSum.x);
    atomicAdd(&sS[c + 1], wSum.y);
    atomicAdd(&sS[c + 2], wSum.z);
    atomicAdd(&sS[c + 3], wSum.w);
    atomicAdd(&sS[128 + c + 0], wSq.x);
    atomicAdd(&sS[128 + c + 1], wSq.y);
    atomicAdd(&sS[128 + c + 2], wSq.z);
    atomicAdd(&sS[128 + c + 3], wSq.w);
    __syncthreads();
    if (threadIdx.x < 256) atomicAdd(&g_stats[threadIdx.x], sS[threadIdx.x]);
}

// ================= final BN + ReLU =================
__global__ void k_epi2(float4* __restrict__ out, int N) {
    __shared__ float sc[128], sh[128];
    if (threadIdx.x < 128) {
        sc[threadIdx.x] = g_scale[threadIdx.x];
        sh[threadIdx.x] = g_shift[threadIdx.x];
    }
    __syncthreads();
    int n4 = N * 32;
    for (int i = blockIdx.x * blockDim.x + threadIdx.x; i < n4;
         i += gridDim.x * blockDim.x) {
        int cq = (i & 31) * 4;
        float4 h = g_H[i];
        float4 o;
        o.x = fmaxf(fmaf(h.x, sc[cq + 0], sh[cq + 0]), 0.f);
        o.y = fmaxf(fmaf(h.y, sc[cq + 1], sh[cq + 1]), 0.f);
        o.z = fmaxf(fmaf(h.z, sc[cq + 2], sh[cq + 2]), 0.f);
        o.w = fmaxf(fmaf(h.w, sc[cq + 3], sh[cq + 3]), 0.f);
        out[i] = o;
    }
}

// ================= launch =================
extern "C" void kernel_launch(void* const* d_in, const int* in_sizes, int n_in,
                              void* d_out, int out_size) {
    const float4* x = (const float4*)d_in[0];
    const void* ei = d_in[1];
    const float* Wl = (const float*)d_in[2];
    const float* Wr = (const float*)d_in[3];
    const float* b = (const float*)d_in[4];
    const float* gamma = (const float*)d_in[5];
    const float* beta = (const float*)d_in[6];

    int N = in_sizes[0] / 128;
    int E = in_sizes[1] / 2;
    int L = in_sizes[4] / 128;
    if (L > 4) L = 4;
    float4* out = (float4*)d_out;
    float invN = 1.0f / (float)N;

    cudaFuncSetAttribute(k_gemm, cudaFuncAttributeMaxDynamicSharedMemorySize, DSM_TOTAL);

    int eb = (E + 255) / 256;
    int nb = (N + 255) / 256;
    int nb1 = (N + 1023) / 1024;

    k_detect<<<1, 32>>>((const long long*)ei, N);
    k_zero_cnt<<<nb, 256>>>(N);
    k_hist<<<eb, 256>>>(ei, E, N);
    k_scan1<<<nb1, 1024>>>(N);
    k_scan2<<<1, 64>>>(nb1);
    k_scan3<<<nb1, 1024>>>(N);
    k_fill<<<eb, 256>>>(ei, E, N);
    k_zero_stats<<<1, 256>>>();
    k_convW<<<(L * 32768 + 255) / 256, 256>>>(Wl, Wr, L);

    int gemmBlocks = (N + 63) / 64;
    for (int l = 0; l < L; l++) {
        k_gemm<<<gemmBlocks, 256, DSM_TOTAL>>>(x, (l == 0) ? 0 : 1, l, N);
        k_aggr<<<1184, 256>>>((const float4*)b + (size_t)l * 32, N);
        k_finstats<<<1, 128>>>(gamma + (size_t)l * 128, beta + (size_t)l * 128, invN);
    }
    k_epi2<<<1184, 256>>>(out, N);
}

// round 16
// speedup vs baseline: 1.1187x; 1.0165x over previous
#include <cuda_runtime.h>
#include <cuda_fp16.h>
#include <cstdint>

#define MAXN 65536
#define MAXE 2097152
#define EPSF 1e-5f
#define PADK 24   // halves per smem row per k-chunk (16 data + 8 pad)

// dynamic smem layout (bytes)
#define ABYTES  (64 * PADK * 2)            // 3072 per split
#define BBYTES  (256 * PADK * 2)           // 12288 per split
#define BUFB    (2 * ABYTES + 2 * BBYTES)  // 30720 per buffer
#define OFF_AH(b) ((b) * BUFB)
#define OFF_AL(b) ((b) * BUFB + ABYTES)
#define OFF_BH(b) ((b) * BUFB + 2 * ABYTES)
#define OFF_BL(b) ((b) * BUFB + 2 * ABYTES + BBYTES)
#define DSM_TOTAL (2 * BUFB + 1024)        // 62464: 2 CTAs/SM

// ================= scratch =================
__device__ uint2  g_Uh[MAXN * 32];    // act(X)@Wl, fp16
__device__ float4 g_V[MAXN * 32];     // act(X)@Wr, fp32
__device__ float4 g_H[MAXN * 32];     // pre-BN activations
__device__ float  g_stats[256];
__device__ float  g_scale[128];
__device__ float  g_shift[128];
__device__ int    g_is64;
__device__ int    g_cnt[MAXN];
__device__ int    g_rowptr[MAXN + 1];
__device__ int    g_colidx[MAXE];
__device__ int    g_btot[64];
__device__ int    g_boff[64];
__device__ int    g_ticket;           // last-block ticket (self-resetting)
__device__ __align__(16) __half g_BTh[4][32768];
__device__ __align__(16) __half g_BTl[4][32768];

__device__ __forceinline__ int edge_at(const void* ei, int which, int e, int E) {
    if (g_is64) return (int)((const long long*)ei)[(size_t)which * E + e];
    return ((const int*)ei)[(size_t)which * E + e];
}
__device__ __forceinline__ void add4(float4& a, const float4& b) {
    a.x += b.x; a.y += b.y; a.z += b.z; a.w += b.w;
}
__device__ __forceinline__ void addh4(float4& a, const uint2& u) {
    float2 lo = __half22float2(*reinterpret_cast<const __half2*>(&u.x));
    float2 hi = __half22float2(*reinterpret_cast<const __half2*>(&u.y));
    a.x += lo.x; a.y += lo.y; a.z += hi.x; a.w += hi.y;
}
__device__ __forceinline__ uint32_t smem_u32(const void* p) {
    uint32_t a;
    asm("{ .reg .u64 t; cvta.to.shared.u64 t, %1; cvt.u32.u64 %0, t; }" : "=r"(a) : "l"(p));
    return a;
}

#define CP_ASYNC16(dst, src) \
    asm volatile("cp.async.cg.shared.global [%0], [%1], 16;" :: "r"(dst), "l"(src))
#define CP_COMMIT() asm volatile("cp.async.commit_group;" ::: "memory")
#define CP_WAIT(n)  asm volatile("cp.async.wait_group %0;" :: "n"(n) : "memory")

#define LDSM4(R, addr)                                                      \
    asm volatile("ldmatrix.sync.aligned.m8n8.x4.shared.b16 {%0,%1,%2,%3}, [%4];" \
                 : "=r"((R)[0]), "=r"((R)[1]), "=r"((R)[2]), "=r"((R)[3])   \
                 : "r"(addr))

#define MMA16816(C, A, B0, B1)                                              \
    asm volatile("mma.sync.aligned.m16n8k16.row.col.f32.f16.f16.f32 "       \
                 "{%0,%1,%2,%3}, {%4,%5,%6,%7}, {%8,%9}, {%0,%1,%2,%3};"    \
                 : "+f"((C)[0]), "+f"((C)[1]), "+f"((C)[2]), "+f"((C)[3])   \
                 : "r"((A)[0]), "r"((A)[1]), "r"((A)[2]), "r"((A)[3]),      \
                   "r"(B0), "r"(B1))

// ================= dtype detect (parallel) =================
__global__ void k_detect(const long long* __restrict__ ei, int N) {
    int i = threadIdx.x;                 // 64 threads
    long long v = ei[i];
    int ok = (v >= 0 && v < (long long)N) ? 1 : 0;
    unsigned m0 = __ballot_sync(0xffffffffu, ok || (threadIdx.x >= 64));
    __shared__ int s_ok[2];
    if ((threadIdx.x & 31) == 0) s_ok[threadIdx.x >> 5] = (m0 == 0xffffffffu);
    __syncthreads();
    if (threadIdx.x == 0) g_is64 = (s_ok[0] && s_ok[1]) ? 1 : 0;
}

// ================= CSR build =================
__global__ void k_zero_cnt(int N) {
    int i = blockIdx.x * blockDim.x + threadIdx.x;
    if (i < N) g_cnt[i] = 0;
    if (i == 0) { g_ticket = 0; }
    if (i < 256) g_stats[i] = 0.f;
}
__global__ void k_hist(const void* __restrict__ ei, int E, int N) {
    int i = blockIdx.x * blockDim.x + threadIdx.x;
    if (i < E) {
        int d = edge_at(ei, 1, i, E);
        if ((unsigned)d < (unsigned)N) atomicAdd(&g_cnt[d], 1);
    }
}
__global__ __launch_bounds__(1024)
void k_scan1(int N) {
    __shared__ int wsum[32];
    int i = blockIdx.x * 1024 + threadIdx.x;
    int lane = threadIdx.x & 31, wid = threadIdx.x >> 5;
    int v = (i < N) ? g_cnt[i] : 0;
    int x = v;
#pragma unroll
    for (int o = 1; o < 32; o <<= 1) {
        int y = __shfl_up_sync(0xffffffffu, x, o);
        if (lane >= o) x += y;
    }
    if (lane == 31) wsum[wid] = x;
    __syncthreads();
    if (wid == 0) {
        int w = wsum[lane];
#pragma unroll
        for (int o = 1; o < 32; o <<= 1) {
            int y = __shfl_up_sync(0xffffffffu, w, o);
            if (lane >= o) w += y;
        }
        wsum[lane] = w;
    }
    __syncthreads();
    int incl = x + (wid > 0 ? wsum[wid - 1] : 0);
    if (i < N) g_rowptr[i + 1] = incl;
    if (threadIdx.x == 1023) g_btot[blockIdx.x] = incl;
}
__global__ void k_scan2(int nb) {
    __shared__ int w0tot;
    int lane = threadIdx.x & 31, wid = threadIdx.x >> 5;
    int v = (threadIdx.x < nb) ? g_btot[threadIdx.x] : 0;
    int x = v;
#pragma unroll
    for (int o = 1; o < 32; o <<= 1) {
        int y = __shfl_up_sync(0xffffffffu, x, o);
        if (lane >= o) x += y;
    }
    if (wid == 0 && lane == 31) w0tot = x;
    __syncthreads();
    int excl = x - v + (wid == 1 ? w0tot : 0);
    if (threadIdx.x < nb) g_boff[threadIdx.x] = excl;
    if (threadIdx.x == 0) g_rowptr[0] = 0;
}
__global__ __launch_bounds__(1024)
void k_scan3(int N) {
    int i = blockIdx.x * 1024 + threadIdx.x;
    if (i < N) g_rowptr[i + 1] += g_boff[blockIdx.x];
}
// destructive fill: rowptr[d] becomes original rowptr[d+1] after this kernel.
__global__ void k_fill(const void* __restrict__ ei, int E, int N) {
    int i = blockIdx.x * blockDim.x + threadIdx.x;
    if (i < E) {
        int s = edge_at(ei, 0, i, E);
        int d = edge_at(ei, 1, i, E);
        if ((unsigned)s >= (unsigned)N || (unsigned)d >= (unsigned)N) return;
        int pos = atomicAdd(&g_rowptr[d], 1);
        if (pos < MAXE) g_colidx[pos] = s;
    }
}

// ================= weight transpose + fp16 split (once) =================
__global__ void k_convW(const float* __restrict__ Wl, const float* __restrict__ Wr, int L) {
    int idx = blockIdx.x * blockDim.x + threadIdx.x;
    if (idx >= L * 32768) return;
    int l = idx >> 15;
    int r = idx & 32767;
    int n = r >> 7, k = r & 127;
    float v = (n < 128) ? Wl[(size_t)l * 16384 + k * 128 + n]
                        : Wr[(size_t)l * 16384 + k * 128 + (n - 128)];
    __half h = __float2half_rn(v);
    __half lo = __float2half_rn(v - __half2float(h));
    g_BTh[l][n * 128 + k] = h;
    g_BTl[l][n * 128 + k] = lo;
}

// ================= HMMA dual GEMM (cp.async double-buffered B, k-chunk 16) ====
__global__ __launch_bounds__(256, 2)
void k_gemm(const float4* __restrict__ Xext, int applyBN, int layer, int Nn) {
    extern __shared__ __align__(16) unsigned char dsm[];
    const uint32_t sbase = smem_u32(dsm);
    float* s_sc = (float*)(dsm + 2 * BUFB);
    float* s_sh = s_sc + 128;

    const int tid = threadIdx.x;
    const int lane = tid & 31;
    const int wid = tid >> 5;
    const int warp_m = wid >> 2;      // 0..1
    const int warp_n = wid & 3;       // 0..3
    const int rowBase = blockIdx.x * 64;
    const float4* __restrict__ X = applyBN ? g_H : Xext;
    const uint4* __restrict__ BTh4 = (const uint4*)g_BTh[layer];
    const uint4* __restrict__ BTl4 = (const uint4*)g_BTl[layer];

    if (applyBN && tid < 128) { s_sc[tid] = g_scale[tid]; s_sh[tid] = g_shift[tid]; }
    __syncthreads();

    float acc[2][8][4];
#pragma unroll
    for (int mi = 0; mi < 2; mi++)
#pragma unroll
        for (int ni = 0; ni < 8; ni++)
#pragma unroll
            for (int j = 0; j < 4; j++) acc[mi][ni][j] = 0.f;

    const uint32_t aOff = ((warp_m * 32 + (lane & 15)) * PADK + (lane >> 4) * 8) * 2;
    const uint32_t bOff = ((warp_n * 64 + (lane & 7) + ((lane >> 4) << 3)) * PADK
                          + ((lane >> 3) & 1) * 8) * 2;

    const int stR = tid >> 2, stQ = tid & 3;
    const int stGrow = rowBase + stR;
    const bool inRange = stGrow < Nn;
    const int bn0 = tid >> 1, bjj = tid & 1;
    const uint32_t bDst0 = (uint32_t)(bn0 * PADK + bjj * 8) * 2;
    const uint32_t bDst1 = (uint32_t)((bn0 + 128) * PADK + bjj * 8) * 2;

    // ---- prologue ----
    CP_ASYNC16(sbase + OFF_BH(0) + bDst0, BTh4 + bn0 * 16 + bjj);
    CP_ASYNC16(sbase + OFF_BH(0) + bDst1, BTh4 + (bn0 + 128) * 16 + bjj);
    CP_ASYNC16(sbase + OFF_BL(0) + bDst0, BTl4 + bn0 * 16 + bjj);
    CP_ASYNC16(sbase + OFF_BL(0) + bDst1, BTl4 + (bn0 + 128) * 16 + bjj);
    CP_COMMIT();
    float4 pA = make_float4(0.f, 0.f, 0.f, 0.f);
    if (inRange) pA = X[(size_t)stGrow * 32 + stQ];

#pragma unroll
    for (int kc = 0; kc < 8; kc++) {
        const int b = kc & 1;
        {
            float4 xv = pA;
            if (applyBN) {
                int cb = (kc * 4 + stQ) * 4;
                xv.x = fmaxf(fmaf(xv.x, s_sc[cb + 0], s_sh[cb + 0]), 0.f);
                xv.y = fmaxf(fmaf(xv.y, s_sc[cb + 1], s_sh[cb + 1]), 0.f);
                xv.z = fmaxf(fmaf(xv.z, s_sc[cb + 2], s_sh[cb + 2]), 0.f);
                xv.w = fmaxf(fmaf(xv.w, s_sc[cb + 3], s_sh[cb + 3]), 0.f);
            }
            __half hx = __float2half_rn(xv.x), hy = __float2half_rn(xv.y);
            __half hz = __float2half_rn(xv.z), hw = __float2half_rn(xv.w);
            __half2 ph01 = __halves2half2(hx, hy);
            __half2 ph23 = __halves2half2(hz, hw);
            __half2 pl01 = __halves2half2(__float2half_rn(xv.x - __half2float(hx)),
                                          __float2half_rn(xv.y - __half2float(hy)));
            __half2 pl23 = __halves2half2(__float2half_rn(xv.z - __half2float(hz)),
                                          __float2half_rn(xv.w - __half2float(hw)));
            uint2 ph, pl;
            ph.x = *reinterpret_cast<unsigned*>(&ph01);
            ph.y = *reinterpret_cast<unsigned*>(&ph23);
            pl.x = *reinterpret_cast<unsigned*>(&pl01);
            pl.y = *reinterpret_cast<unsigned*>(&pl23);
            *(uint2*)(dsm + OFF_AH(b) + (stR * PADK + stQ * 4) * 2) = ph;
            *(uint2*)(dsm + OFF_AL(b) + (stR * PADK + stQ * 4) * 2) = pl;
        }
        if (kc < 7) {
            const int kn = kc + 1;
            const int nb2 = 1 - b;
            CP_ASYNC16(sbase + OFF_BH(nb2) + bDst0, BTh4 + bn0 * 16 + kn * 2 + bjj);
            CP_ASYNC16(sbase + OFF_BH(nb2) + bDst1, BTh4 + (bn0 + 128) * 16 + kn * 2 + bjj);
            CP_ASYNC16(sbase + OFF_BL(nb2) + bDst0, BTl4 + bn0 * 16 + kn * 2 + bjj);
            CP_ASYNC16(sbase + OFF_BL(nb2) + bDst1, BTl4 + (bn0 + 128) * 16 + kn * 2 + bjj);
            CP_COMMIT();
            if (inRange) pA = X[(size_t)stGrow * 32 + kn * 4 + stQ];
            CP_WAIT(1);
        } else {
            CP_WAIT(0);
        }
        __syncthreads();

        const uint32_t aShB = sbase + OFF_AH(b), aSlB = sbase + OFF_AL(b);
        const uint32_t bShB = sbase + OFF_BH(b), bSlB = sbase + OFF_BL(b);
        uint32_t ah[2][4], al[2][4], bb[8][2];
#pragma unroll
        for (int mi = 0; mi < 2; mi++) {
            LDSM4(ah[mi], aShB + aOff + mi * (16 * PADK * 2));
            LDSM4(al[mi], aSlB + aOff + mi * (16 * PADK * 2));
        }
#pragma unroll
        for (int p = 0; p < 4; p++) {
            uint32_t t4[4];
            LDSM4(t4, bShB + bOff + p * (16 * PADK * 2));
            bb[2 * p][0] = t4[0]; bb[2 * p][1] = t4[1];
            bb[2 * p + 1][0] = t4[2]; bb[2 * p + 1][1] = t4[3];
        }
#pragma unroll
        for (int mi = 0; mi < 2; mi++)
#pragma unroll
            for (int ni = 0; ni < 8; ni++) {
                MMA16816(acc[mi][ni], ah[mi], bb[ni][0], bb[ni][1]);
                MMA16816(acc[mi][ni], al[mi], bb[ni][0], bb[ni][1]);
            }
#pragma unroll
        for (int p = 0; p < 4; p++) {
            uint32_t t4[4];
            LDSM4(t4, bSlB + bOff + p * (16 * PADK * 2));
            bb[2 * p][0] = t4[0]; bb[2 * p][1] = t4[1];
            bb[2 * p + 1][0] = t4[2]; bb[2 * p + 1][1] = t4[3];
        }
#pragma unroll
        for (int mi = 0; mi < 2; mi++)
#pragma unroll
            for (int ni = 0; ni < 8; ni++)
                MMA16816(acc[mi][ni], ah[mi], bb[ni][0], bb[ni][1]);
        __syncthreads();
    }

    // ---- epilogue ----
    __half* Uh = (__half*)g_Uh;
    float* Vf = (float*)g_V;
#pragma unroll
    for (int mi = 0; mi < 2; mi++) {
        int r0 = rowBase + warp_m * 32 + mi * 16 + (lane >> 2);
        int r1 = r0 + 8;
#pragma unroll
        for (int ni = 0; ni < 8; ni++) {
            int col = warp_n * 64 + ni * 8 + (lane & 3) * 2;
            float c0 = acc[mi][ni][0], c1 = acc[mi][ni][1];
            float c2 = acc[mi][ni][2], c3 = acc[mi][ni][3];
            if (col < 128) {
                if (r0 < Nn)
                    *(__half2*)(Uh + (size_t)r0 * 128 + col) = __floats2half2_rn(c0, c1);
                if (r1 < Nn)
                    *(__half2*)(Uh + (size_t)r1 * 128 + col) = __floats2half2_rn(c2, c3);
            } else {
                int cv = col - 128;
                if (r0 < Nn)
                    *(float2*)(Vf + (size_t)r0 * 128 + cv) = make_float2(c0, c1);
                if (r1 < Nn)
                    *(float2*)(Vf + (size_t)r1 * 128 + cv) = make_float2(c2, c3);
            }
        }
    }
}

// ====== gather-mean (fp16 U) + bias + BN stats + fused finstats (ticket) ======
// rowptr shifted by k_fill: row d spans [rowptr[d-1], rowptr[d]) (row 0 from 0).
__global__ __launch_bounds__(256)
void k_aggr(const float4* __restrict__ b4, const float* __restrict__ gamma,
            const float* __restrict__ beta, float invN, int N) {
    __shared__ float sS[256];
    __shared__ int s_last;
    if (threadIdx.x < 256) sS[threadIdx.x] = 0.f;
    __syncthreads();

    const int lane = threadIdx.x & 31;
    const int gwarp = blockIdx.x * (blockDim.x >> 5) + (threadIdx.x >> 5);
    const int nWarps = gridDim.x * (blockDim.x >> 5);

    const float4 z4 = make_float4(0.f, 0.f, 0.f, 0.f);
    float4 wSum = z4, wSq = z4;
    const float4 bv = b4[lane];

    for (int node = gwarp; node < N; node += nWarps) {
        int beg = (node == 0) ? 0 : g_rowptr[node - 1];
        int end = g_rowptr[node];
        float4 acc0 = z4, acc1 = z4, acc2 = z4, acc3 = z4;
        int e = beg;
        for (; e + 3 < end; e += 4) {
            int s0 = g_colidx[e];
            int s1 = g_colidx[e + 1];
            int s2 = g_colidx[e + 2];
            int s3 = g_colidx[e + 3];
            uint2 u0 = g_Uh[(size_t)s0 * 32 + lane];
            uint2 u1 = g_Uh[(size_t)s1 * 32 + lane];
            uint2 u2 = g_Uh[(size_t)s2 * 32 + lane];
            uint2 u3 = g_Uh[(size_t)s3 * 32 + lane];
            addh4(acc0, u0);
            addh4(acc1, u1);
            addh4(acc2, u2);
            addh4(acc3, u3);
        }
        for (; e < end; e++) addh4(acc0, g_Uh[(size_t)g_colidx[e] * 32 + lane]);
        add4(acc0, acc1);
        add4(acc2, acc3);
        add4(acc0, acc2);

        float di = 1.0f / fmaxf((float)(end - beg), 1.0f);
        float4 v = g_V[(size_t)node * 32 + lane];
        float4 h;
        h.x = fmaf(acc0.x, di, v.x) + bv.x;
        h.y = fmaf(acc0.y, di, v.y) + bv.y;
        h.z = fmaf(acc0.z, di, v.z) + bv.z;
        h.w = fmaf(acc0.w, di, v.w) + bv.w;
        g_H[(size_t)node * 32 + lane] = h;

        add4(wSum, h);
        wSq.x = fmaf(h.x, h.x, wSq.x);
        wSq.y = fmaf(h.y, h.y, wSq.y);
        wSq.z = fmaf(h.z, h.z, wSq.z);
        wSq.w = fmaf(h.w, h.w, wSq.w);
    }

    int c = lane * 4;
    atomicAdd(&sS[c + 0], wSum.x);
    atomicAdd(&sS[c + 1], wSum.y);
    atomicAdd(&sS[c + 2], wSum.z);
    atomicAdd(&sS[c + 3], wSum.w);
    atomicAdd(&sS[128 + c + 0], wSq.x);
    atomicAdd(&sS[128 + c + 1], wSq.y);
    atomicAdd(&sS[128 + c + 2], wSq.z);
    atomicAdd(&sS[128 + c + 3], wSq.w);
    __syncthreads();
    if (threadIdx.x < 256) atomicAdd(&g_stats[threadIdx.x], sS[threadIdx.x]);

    // ---- fused finstats: last block converts stats -> scale/shift ----
    __threadfence();
    if (threadIdx.x == 0)
        s_last = (atomicAdd(&g_ticket, 1) == gridDim.x - 1) ? 1 : 0;
    __syncthreads();
    if (s_last) {
        if (threadIdx.x < 128) {
            int cc = threadIdx.x;
            float mu = g_stats[cc] * invN;
            float var = g_stats[128 + cc] * invN - mu * mu;
            float s = gamma[cc] * rsqrtf(var + EPSF);
            g_scale[cc] = s;
            g_shift[cc] = beta[cc] - mu * s;
            g_stats[cc] = 0.f;
            g_stats[128 + cc] = 0.f;
        }
        if (threadIdx.x == 0) g_ticket = 0;
    }
}

// ================= final BN + ReLU =================
__global__ void k_epi2(float4* __restrict__ out, int N) {
    __shared__ float sc[128], sh[128];
    if (threadIdx.x < 128) {
        sc[threadIdx.x] = g_scale[threadIdx.x];
        sh[threadIdx.x] = g_shift[threadIdx.x];
    }
    __syncthreads();
    int n4 = N * 32;
    for (int i = blockIdx.x * blockDim.x + threadIdx.x; i < n4;
         i += gridDim.x * blockDim.x) {
        int cq = (i & 31) * 4;
        float4 h = g_H[i];
        float4 o;
        o.x = fmaxf(fmaf(h.x, sc[cq + 0], sh[cq + 0]), 0.f);
        o.y = fmaxf(fmaf(h.y, sc[cq + 1], sh[cq + 1]), 0.f);
        o.z = fmaxf(fmaf(h.z, sc[cq + 2], sh[cq + 2]), 0.f);
        o.w = fmaxf(fmaf(h.w, sc[cq + 3], sh[cq + 3]), 0.f);
        out[i] = o;
    }
}

// ================= launch =================
extern "C" void kernel_launch(void* const* d_in, const int* in_sizes, int n_in,
                              void* d_out, int out_size) {
    const float4* x = (const float4*)d_in[0];
    const void* ei = d_in[1];
    const float* Wl = (const float*)d_in[2];
    const float* Wr = (const float*)d_in[3];
    const float* b = (const float*)d_in[4];
    const float* gamma = (const float*)d_in[5];
    const float* beta = (const float*)d_in[6];

    int N = in_sizes[0] / 128;
    int E = in_sizes[1] / 2;
    int L = in_sizes[4] / 128;
    if (L > 4) L = 4;
    float4* out = (float4*)d_out;
    float invN = 1.0f / (float)N;

    cudaFuncSetAttribute(k_gemm, cudaFuncAttributeMaxDynamicSharedMemorySize, DSM_TOTAL);

    int eb = (E + 255) / 256;
    int nb = (N + 255) / 256;
    int nb1 = (N + 1023) / 1024;

    k_detect<<<1, 64>>>((const long long*)ei, N);
    k_zero_cnt<<<nb, 256>>>(N);
    k_hist<<<eb, 256>>>(ei, E, N);
    k_scan1<<<nb1, 1024>>>(N);
    k_scan2<<<1, 64>>>(nb1);
    k_scan3<<<nb1, 1024>>>(N);
    k_fill<<<eb, 256>>>(ei, E, N);
    k_convW<<<(L * 32768 + 255) / 256, 256>>>(Wl, Wr, L);

    int gemmBlocks = (N + 63) / 64;
    for (int l = 0; l < L; l++) {
        k_gemm<<<gemmBlocks, 256, DSM_TOTAL>>>(x, (l == 0) ? 0 : 1, l, N);
        k_aggr<<<1184, 256>>>((const float4*)b + (size_t)l * 32,
                              gamma + (size_t)l * 128, beta + (size_t)l * 128, invN, N);
    }
    k_epi2<<<1184, 256>>>(out, N);
}

// round 17
// speedup vs baseline: 1.1748x; 1.0502x over previous
#include <cuda_runtime.h>
#include <cuda_fp16.h>
#include <cstdint>

#define MAXN 65536
#define MAXE 2097152
#define EPSF 1e-5f
#define PADK 24   // halves per smem row per k-chunk (16 data + 8 pad)

// dynamic smem layout (bytes)
#define ABYTES  (64 * PADK * 2)            // 3072 per split
#define BBYTES  (256 * PADK * 2)           // 12288 per split
#define BUFB    (2 * ABYTES + 2 * BBYTES)  // 30720 per buffer
#define OFF_AH(b) ((b) * BUFB)
#define OFF_AL(b) ((b) * BUFB + ABYTES)
#define OFF_BH(b) ((b) * BUFB + 2 * ABYTES)
#define OFF_BL(b) ((b) * BUFB + 2 * ABYTES + BBYTES)
#define DSM_TOTAL (2 * BUFB + 1024)        // 62464: 2 CTAs/SM

// ================= scratch =================
__device__ uint2  g_Uh[MAXN * 32];    // act(X)@Wl, fp16
__device__ float4 g_V[MAXN * 32];     // act(X)@Wr, fp32
__device__ float4 g_H[MAXN * 32];     // pre-BN activations
__device__ float  g_stats[256];
__device__ float  g_scale[128];
__device__ float  g_shift[128];
__device__ int    g_is64;
__device__ int    g_cnt[MAXN];
__device__ int    g_rowptr[MAXN + 1];
__device__ int    g_colidx[MAXE];
__device__ int    g_btot[64];
__device__ int    g_boff[64];
__device__ int    g_ticket;           // last-block ticket (self-resetting)
__device__ __align__(16) __half g_BTh[4][32768];
__device__ __align__(16) __half g_BTl[4][32768];

__device__ __forceinline__ int edge_at(const void* ei, int which, int e, int E) {
    if (g_is64) return (int)((const long long*)ei)[(size_t)which * E + e];
    return ((const int*)ei)[(size_t)which * E + e];
}
__device__ __forceinline__ void add4(float4& a, const float4& b) {
    a.x += b.x; a.y += b.y; a.z += b.z; a.w += b.w;
}
__device__ __forceinline__ void addh4(float4& a, const uint2& u) {
    float2 lo = __half22float2(*reinterpret_cast<const __half2*>(&u.x));
    float2 hi = __half22float2(*reinterpret_cast<const __half2*>(&u.y));
    a.x += lo.x; a.y += lo.y; a.z += hi.x; a.w += hi.y;
}
__device__ __forceinline__ uint32_t smem_u32(const void* p) {
    uint32_t a;
    asm("{ .reg .u64 t; cvta.to.shared.u64 t, %1; cvt.u32.u64 %0, t; }" : "=r"(a) : "l"(p));
    return a;
}

#define CP_ASYNC16(dst, src) \
    asm volatile("cp.async.cg.shared.global [%0], [%1], 16;" :: "r"(dst), "l"(src))
#define CP_COMMIT() asm volatile("cp.async.commit_group;" ::: "memory")
#define CP_WAIT(n)  asm volatile("cp.async.wait_group %0;" :: "n"(n) : "memory")

#define LDSM4(R, addr)                                                      \
    asm volatile("ldmatrix.sync.aligned.m8n8.x4.shared.b16 {%0,%1,%2,%3}, [%4];" \
                 : "=r"((R)[0]), "=r"((R)[1]), "=r"((R)[2]), "=r"((R)[3])   \
                 : "r"(addr))

#define MMA16816(C, A, B0, B1)                                              \
    asm volatile("mma.sync.aligned.m16n8k16.row.col.f32.f16.f16.f32 "       \
                 "{%0,%1,%2,%3}, {%4,%5,%6,%7}, {%8,%9}, {%0,%1,%2,%3};"    \
                 : "+f"((C)[0]), "+f"((C)[1]), "+f"((C)[2]), "+f"((C)[3])   \
                 : "r"((A)[0]), "r"((A)[1]), "r"((A)[2]), "r"((A)[3]),      \
                   "r"(B0), "r"(B1))

// ================= dtype detect (parallel) =================
__global__ void k_detect(const long long* __restrict__ ei, int N) {
    int i = threadIdx.x;                 // 64 threads
    long long v = ei[i];
    int ok = (v >= 0 && v < (long long)N) ? 1 : 0;
    unsigned m0 = __ballot_sync(0xffffffffu, ok || (threadIdx.x >= 64));
    __shared__ int s_ok[2];
    if ((threadIdx.x & 31) == 0) s_ok[threadIdx.x >> 5] = (m0 == 0xffffffffu);
    __syncthreads();
    if (threadIdx.x == 0) g_is64 = (s_ok[0] && s_ok[1]) ? 1 : 0;
}

// ================= CSR build =================
__global__ void k_zero_cnt(int N) {
    int i = blockIdx.x * blockDim.x + threadIdx.x;
    if (i < N) g_cnt[i] = 0;
    if (i == 0) { g_ticket = 0; }
    if (i < 256) g_stats[i] = 0.f;
}
__global__ void k_hist(const void* __restrict__ ei, int E, int N) {
    int i = blockIdx.x * blockDim.x + threadIdx.x;
    if (i < E) {
        int d = edge_at(ei, 1, i, E);
        if ((unsigned)d < (unsigned)N) atomicAdd(&g_cnt[d], 1);
    }
}
__global__ __launch_bounds__(1024)
void k_scan1(int N) {
    __shared__ int wsum[32];
    int i = blockIdx.x * 1024 + threadIdx.x;
    int lane = threadIdx.x & 31, wid = threadIdx.x >> 5;
    int v = (i < N) ? g_cnt[i] : 0;
    int x = v;
#pragma unroll
    for (int o = 1; o < 32; o <<= 1) {
        int y = __shfl_up_sync(0xffffffffu, x, o);
        if (lane >= o) x += y;
    }
    if (lane == 31) wsum[wid] = x;
    __syncthreads();
    if (wid == 0) {
        int w = wsum[lane];
#pragma unroll
        for (int o = 1; o < 32; o <<= 1) {
            int y = __shfl_up_sync(0xffffffffu, w, o);
            if (lane >= o) w += y;
        }
        wsum[lane] = w;
    }
    __syncthreads();
    int incl = x + (wid > 0 ? wsum[wid - 1] : 0);
    if (i < N) g_rowptr[i + 1] = incl;
    if (threadIdx.x == 1023) g_btot[blockIdx.x] = incl;
}
__global__ void k_scan2(int nb) {
    __shared__ int w0tot;
    int lane = threadIdx.x & 31, wid = threadIdx.x >> 5;
    int v = (threadIdx.x < nb) ? g_btot[threadIdx.x] : 0;
    int x = v;
#pragma unroll
    for (int o = 1; o < 32; o <<= 1) {
        int y = __shfl_up_sync(0xffffffffu, x, o);
        if (lane >= o) x += y;
    }
    if (wid == 0 && lane == 31) w0tot = x;
    __syncthreads();
    int excl = x - v + (wid == 1 ? w0tot : 0);
    if (threadIdx.x < nb) g_boff[threadIdx.x] = excl;
    if (threadIdx.x == 0) g_rowptr[0] = 0;
}
__global__ __launch_bounds__(1024)
void k_scan3(int N) {
    int i = blockIdx.x * 1024 + threadIdx.x;
    if (i < N) g_rowptr[i + 1] += g_boff[blockIdx.x];
}
// destructive fill: rowptr[d] becomes original rowptr[d+1] after this kernel.
__global__ void k_fill(const void* __restrict__ ei, int E, int N) {
    int i = blockIdx.x * blockDim.x + threadIdx.x;
    if (i < E) {
        int s = edge_at(ei, 0, i, E);
        int d = edge_at(ei, 1, i, E);
        if ((unsigned)s >= (unsigned)N || (unsigned)d >= (unsigned)N) return;
        int pos = atomicAdd(&g_rowptr[d], 1);
        if (pos < MAXE) g_colidx[pos] = s;
    }
}

// ================= weight transpose + fp16 split (once) =================
__global__ void k_convW(const float* __restrict__ Wl, const float* __restrict__ Wr, int L) {
    int idx = blockIdx.x * blockDim.x + threadIdx.x;
    if (idx >= L * 32768) return;
    int l = idx >> 15;
    int r = idx & 32767;
    int n = r >> 7, k = r & 127;
    float v = (n < 128) ? Wl[(size_t)l * 16384 + k * 128 + n]
                        : Wr[(size_t)l * 16384 + k * 128 + (n - 128)];
    __half h = __float2half_rn(v);
    __half lo = __float2half_rn(v - __half2float(h));
    g_BTh[l][n * 128 + k] = h;
    g_BTl[l][n * 128 + k] = lo;
}

// ================= HMMA dual GEMM (cp.async double-buffered B, k-chunk 16) ====
__global__ __launch_bounds__(256, 2)
void k_gemm(const float4* __restrict__ Xext, int applyBN, int layer, int Nn) {
    extern __shared__ __align__(16) unsigned char dsm[];
    const uint32_t sbase = smem_u32(dsm);
    float* s_sc = (float*)(dsm + 2 * BUFB);
    float* s_sh = s_sc + 128;

    const int tid = threadIdx.x;
    const int lane = tid & 31;
    const int wid = tid >> 5;
    const int warp_m = wid >> 2;      // 0..1
    const int warp_n = wid & 3;       // 0..3
    const int rowBase = blockIdx.x * 64;
    const float4* __restrict__ X = applyBN ? g_H : Xext;
    const uint4* __restrict__ BTh4 = (const uint4*)g_BTh[layer];
    const uint4* __restrict__ BTl4 = (const uint4*)g_BTl[layer];

    if (applyBN && tid < 128) { s_sc[tid] = g_scale[tid]; s_sh[tid] = g_shift[tid]; }
    __syncthreads();

    float acc[2][8][4];
#pragma unroll
    for (int mi = 0; mi < 2; mi++)
#pragma unroll
        for (int ni = 0; ni < 8; ni++)
#pragma unroll
            for (int j = 0; j < 4; j++) acc[mi][ni][j] = 0.f;

    const uint32_t aOff = ((warp_m * 32 + (lane & 15)) * PADK + (lane >> 4) * 8) * 2;
    const uint32_t bOff = ((warp_n * 64 + (lane & 7) + ((lane >> 4) << 3)) * PADK
                          + ((lane >> 3) & 1) * 8) * 2;

    const int stR = tid >> 2, stQ = tid & 3;
    const int stGrow = rowBase + stR;
    const bool inRange = stGrow < Nn;
    const int bn0 = tid >> 1, bjj = tid & 1;
    const uint32_t bDst0 = (uint32_t)(bn0 * PADK + bjj * 8) * 2;
    const uint32_t bDst1 = (uint32_t)((bn0 + 128) * PADK + bjj * 8) * 2;

    // ---- prologue ----
    CP_ASYNC16(sbase + OFF_BH(0) + bDst0, BTh4 + bn0 * 16 + bjj);
    CP_ASYNC16(sbase + OFF_BH(0) + bDst1, BTh4 + (bn0 + 128) * 16 + bjj);
    CP_ASYNC16(sbase + OFF_BL(0) + bDst0, BTl4 + bn0 * 16 + bjj);
    CP_ASYNC16(sbase + OFF_BL(0) + bDst1, BTl4 + (bn0 + 128) * 16 + bjj);
    CP_COMMIT();
    float4 pA = make_float4(0.f, 0.f, 0.f, 0.f);
    if (inRange) pA = X[(size_t)stGrow * 32 + stQ];

#pragma unroll
    for (int kc = 0; kc < 8; kc++) {
        const int b = kc & 1;
        {
            float4 xv = pA;
            if (applyBN) {
                int cb = (kc * 4 + stQ) * 4;
                xv.x = fmaxf(fmaf(xv.x, s_sc[cb + 0], s_sh[cb + 0]), 0.f);
                xv.y = fmaxf(fmaf(xv.y, s_sc[cb + 1], s_sh[cb + 1]), 0.f);
                xv.z = fmaxf(fmaf(xv.z, s_sc[cb + 2], s_sh[cb + 2]), 0.f);
                xv.w = fmaxf(fmaf(xv.w, s_sc[cb + 3], s_sh[cb + 3]), 0.f);
            }
            __half hx = __float2half_rn(xv.x), hy = __float2half_rn(xv.y);
            __half hz = __float2half_rn(xv.z), hw = __float2half_rn(xv.w);
            __half2 ph01 = __halves2half2(hx, hy);
            __half2 ph23 = __halves2half2(hz, hw);
            __half2 pl01 = __halves2half2(__float2half_rn(xv.x - __half2float(hx)),
                                          __float2half_rn(xv.y - __half2float(hy)));
            __half2 pl23 = __halves2half2(__float2half_rn(xv.z - __half2float(hz)),
                                          __float2half_rn(xv.w - __half2float(hw)));
            uint2 ph, pl;
            ph.x = *reinterpret_cast<unsigned*>(&ph01);
            ph.y = *reinterpret_cast<unsigned*>(&ph23);
            pl.x = *reinterpret_cast<unsigned*>(&pl01);
            pl.y = *reinterpret_cast<unsigned*>(&pl23);
            *(uint2*)(dsm + OFF_AH(b) + (stR * PADK + stQ * 4) * 2) = ph;
            *(uint2*)(dsm + OFF_AL(b) + (stR * PADK + stQ * 4) * 2) = pl;
        }
        if (kc < 7) {
            const int kn = kc + 1;
            const int nb2 = 1 - b;
            CP_ASYNC16(sbase + OFF_BH(nb2) + bDst0, BTh4 + bn0 * 16 + kn * 2 + bjj);
            CP_ASYNC16(sbase + OFF_BH(nb2) + bDst1, BTh4 + (bn0 + 128) * 16 + kn * 2 + bjj);
            CP_ASYNC16(sbase + OFF_BL(nb2) + bDst0, BTl4 + bn0 * 16 + kn * 2 + bjj);
            CP_ASYNC16(sbase + OFF_BL(nb2) + bDst1, BTl4 + (bn0 + 128) * 16 + kn * 2 + bjj);
            CP_COMMIT();
            if (inRange) pA = X[(size_t)stGrow * 32 + kn * 4 + stQ];
            CP_WAIT(1);
        } else {
            CP_WAIT(0);
        }
        __syncthreads();

        const uint32_t aShB = sbase + OFF_AH(b), aSlB = sbase + OFF_AL(b);
        const uint32_t bShB = sbase + OFF_BH(b), bSlB = sbase + OFF_BL(b);
        uint32_t ah[2][4], al[2][4], bb[8][2];
#pragma unroll
        for (int mi = 0; mi < 2; mi++) {
            LDSM4(ah[mi], aShB + aOff + mi * (16 * PADK * 2));
            LDSM4(al[mi], aSlB + aOff + mi * (16 * PADK * 2));
        }
#pragma unroll
        for (int p = 0; p < 4; p++) {
            uint32_t t4[4];
            LDSM4(t4, bShB + bOff + p * (16 * PADK * 2));
            bb[2 * p][0] = t4[0]; bb[2 * p][1] = t4[1];
            bb[2 * p + 1][0] = t4[2]; bb[2 * p + 1][1] = t4[3];
        }
#pragma unroll
        for (int mi = 0; mi < 2; mi++)
#pragma unroll
            for (int ni = 0; ni < 8; ni++) {
                MMA16816(acc[mi][ni], ah[mi], bb[ni][0], bb[ni][1]);
                MMA16816(acc[mi][ni], al[mi], bb[ni][0], bb[ni][1]);
            }
#pragma unroll
        for (int p = 0; p < 4; p++) {
            uint32_t t4[4];
            LDSM4(t4, bSlB + bOff + p * (16 * PADK * 2));
            bb[2 * p][0] = t4[0]; bb[2 * p][1] = t4[1];
            bb[2 * p + 1][0] = t4[2]; bb[2 * p + 1][1] = t4[3];
        }
#pragma unroll
        for (int mi = 0; mi < 2; mi++)
#pragma unroll
            for (int ni = 0; ni < 8; ni++)
                MMA16816(acc[mi][ni], ah[mi], bb[ni][0], bb[ni][1]);
        __syncthreads();
    }

    // ---- epilogue ----
    __half* Uh = (__half*)g_Uh;
    float* Vf = (float*)g_V;
#pragma unroll
    for (int mi = 0; mi < 2; mi++) {
        int r0 = rowBase + warp_m * 32 + mi * 16 + (lane >> 2);
        int r1 = r0 + 8;
#pragma unroll
        for (int ni = 0; ni < 8; ni++) {
            int col = warp_n * 64 + ni * 8 + (lane & 3) * 2;
            float c0 = acc[mi][ni][0], c1 = acc[mi][ni][1];
            float c2 = acc[mi][ni][2], c3 = acc[mi][ni][3];
            if (col < 128) {
                if (r0 < Nn)
                    *(__half2*)(Uh + (size_t)r0 * 128 + col) = __floats2half2_rn(c0, c1);
                if (r1 < Nn)
                    *(__half2*)(Uh + (size_t)r1 * 128 + col) = __floats2half2_rn(c2, c3);
            } else {
                int cv = col - 128;
                if (r0 < Nn)
                    *(float2*)(Vf + (size_t)r0 * 128 + cv) = make_float2(c0, c1);
                if (r1 < Nn)
                    *(float2*)(Vf + (size_t)r1 * 128 + cv) = make_float2(c2, c3);
            }
        }
    }
}

// ====== gather-mean (fp16 U) + bias + BN stats + fused finstats (ticket) ======
__global__ __launch_bounds__(256)
void k_aggr(const float4* __restrict__ b4, const float* __restrict__ gamma,
            const float* __restrict__ beta, float invN, int N) {
    __shared__ float sS[256];
    __shared__ int s_last;
    if (threadIdx.x < 256) sS[threadIdx.x] = 0.f;
    __syncthreads();

    const int lane = threadIdx.x & 31;
    const int gwarp = blockIdx.x * (blockDim.x >> 5) + (threadIdx.x >> 5);
    const int nWarps = gridDim.x * (blockDim.x >> 5);

    const float4 z4 = make_float4(0.f, 0.f, 0.f, 0.f);
    float4 wSum = z4, wSq = z4;
    const float4 bv = b4[lane];

    for (int node = gwarp; node < N; node += nWarps) {
        int beg = (node == 0) ? 0 : g_rowptr[node - 1];
        int end = g_rowptr[node];
        float4 acc0 = z4, acc1 = z4, acc2 = z4, acc3 = z4;
        int e = beg;
        for (; e + 3 < end; e += 4) {
            int s0 = g_colidx[e];
            int s1 = g_colidx[e + 1];
            int s2 = g_colidx[e + 2];
            int s3 = g_colidx[e + 3];
            uint2 u0 = g_Uh[(size_t)s0 * 32 + lane];
            uint2 u1 = g_Uh[(size_t)s1 * 32 + lane];
            uint2 u2 = g_Uh[(size_t)s2 * 32 + lane];
            uint2 u3 = g_Uh[(size_t)s3 * 32 + lane];
            addh4(acc0, u0);
            addh4(acc1, u1);
            addh4(acc2, u2);
            addh4(acc3, u3);
        }
        for (; e < end; e++) addh4(acc0, g_Uh[(size_t)g_colidx[e] * 32 + lane]);
        add4(acc0, acc1);
        add4(acc2, acc3);
        add4(acc0, acc2);

        float di = 1.0f / fmaxf((float)(end - beg), 1.0f);
        float4 v = g_V[(size_t)node * 32 + lane];
        float4 h;
        h.x = fmaf(acc0.x, di, v.x) + bv.x;
        h.y = fmaf(acc0.y, di, v.y) + bv.y;
        h.z = fmaf(acc0.z, di, v.z) + bv.z;
        h.w = fmaf(acc0.w, di, v.w) + bv.w;
        g_H[(size_t)node * 32 + lane] = h;

        add4(wSum, h);
        wSq.x = fmaf(h.x, h.x, wSq.x);
        wSq.y = fmaf(h.y, h.y, wSq.y);
        wSq.z = fmaf(h.z, h.z, wSq.z);
        wSq.w = fmaf(h.w, h.w, wSq.w);
    }

    int c = lane * 4;
    atomicAdd(&sS[c + 0], wSum.x);
    atomicAdd(&sS[c + 1], wSum.y);
    atomicAdd(&sS[c + 2], wSum.z);
    atomicAdd(&sS[c + 3], wSum.w);
    atomicAdd(&sS[128 + c + 0], wSq.x);
    atomicAdd(&sS[128 + c + 1], wSq.y);
    atomicAdd(&sS[128 + c + 2], wSq.z);
    atomicAdd(&sS[128 + c + 3], wSq.w);
    __syncthreads();
    if (threadIdx.x < 256) atomicAdd(&g_stats[threadIdx.x], sS[threadIdx.x]);

    __threadfence();
    if (threadIdx.x == 0)
        s_last = (atomicAdd(&g_ticket, 1) == gridDim.x - 1) ? 1 : 0;
    __syncthreads();
    if (s_last) {
        if (threadIdx.x < 128) {
            int cc = threadIdx.x;
            float mu = g_stats[cc] * invN;
            float var = g_stats[128 + cc] * invN - mu * mu;
            float s = gamma[cc] * rsqrtf(var + EPSF);
            g_scale[cc] = s;
            g_shift[cc] = beta[cc] - mu * s;
            g_stats[cc] = 0.f;
            g_stats[128 + cc] = 0.f;
        }
        if (threadIdx.x == 0) g_ticket = 0;
    }
}

// ================= final BN + ReLU =================
__global__ void k_epi2(float4* __restrict__ out, int N) {
    __shared__ float sc[128], sh[128];
    if (threadIdx.x < 128) {
        sc[threadIdx.x] = g_scale[threadIdx.x];
        sh[threadIdx.x] = g_shift[threadIdx.x];
    }
    __syncthreads();
    int n4 = N * 32;
    for (int i = blockIdx.x * blockDim.x + threadIdx.x; i < n4;
         i += gridDim.x * blockDim.x) {
        int cq = (i & 31) * 4;
        float4 h = g_H[i];
        float4 o;
        o.x = fmaxf(fmaf(h.x, sc[cq + 0], sh[cq + 0]), 0.f);
        o.y = fmaxf(fmaf(h.y, sc[cq + 1], sh[cq + 1]), 0.f);
        o.z = fmaxf(fmaf(h.z, sc[cq + 2], sh[cq + 2]), 0.f);
        o.w = fmaxf(fmaf(h.w, sc[cq + 3], sh[cq + 3]), 0.f);
        out[i] = o;
    }
}

// ================= launch =================
extern "C" void kernel_launch(void* const* d_in, const int* in_sizes, int n_in,
                              void* d_out, int out_size) {
    const float4* x = (const float4*)d_in[0];
    const void* ei = d_in[1];
    const float* Wl = (const float*)d_in[2];
    const float* Wr = (const float*)d_in[3];
    const float* b = (const float*)d_in[4];
    const float* gamma = (const float*)d_in[5];
    const float* beta = (const float*)d_in[6];

    int N = in_sizes[0] / 128;
    int E = in_sizes[1] / 2;
    int L = in_sizes[4] / 128;
    if (L > 4) L = 4;
    float4* out = (float4*)d_out;
    float invN = 1.0f / (float)N;

    static cudaStream_t s2 = nullptr;
    static cudaEvent_t evFork = nullptr, evJoin = nullptr;
    if (s2 == nullptr) {
        cudaStreamCreateWithFlags(&s2, cudaStreamNonBlocking);
        cudaEventCreateWithFlags(&evFork, cudaEventDisableTiming);
        cudaEventCreateWithFlags(&evJoin, cudaEventDisableTiming);
        cudaFuncSetAttribute(k_gemm, cudaFuncAttributeMaxDynamicSharedMemorySize, DSM_TOTAL);
    }

    int eb = (E + 255) / 256;
    int nb = (N + 255) / 256;
    int nb1 = (N + 1023) / 1024;
    int gemmBlocks = (N + 63) / 64;

    // ---- fork: CSR build on s2, concurrent with convW + gemm(layer 0) ----
    cudaEventRecord(evFork, 0);
    cudaStreamWaitEvent(s2, evFork, 0);

    k_detect<<<1, 64, 0, s2>>>((const long long*)ei, N);
    k_zero_cnt<<<nb, 256, 0, s2>>>(N);
    k_hist<<<eb, 256, 0, s2>>>(ei, E, N);
    k_scan1<<<nb1, 1024, 0, s2>>>(N);
    k_scan2<<<1, 64, 0, s2>>>(nb1);
    k_scan3<<<nb1, 1024, 0, s2>>>(N);
    k_fill<<<eb, 256, 0, s2>>>(ei, E, N);
    cudaEventRecord(evJoin, s2);

    k_convW<<<(L * 32768 + 255) / 256, 256>>>(Wl, Wr, L);
    k_gemm<<<gemmBlocks, 256, DSM_TOTAL>>>(x, 0, 0, N);

    // ---- join before first aggr (needs CSR) ----
    cudaStreamWaitEvent(0, evJoin, 0);

    for (int l = 0; l < L; l++) {
        if (l > 0)
            k_gemm<<<gemmBlocks, 256, DSM_TOTAL>>>(x, 1, l, N);
        k_aggr<<<1184, 256>>>((const float4*)b + (size_t)l * 32,
                              gamma + (size_t)l * 128, beta + (size_t)l * 128, invN, N);
    }
    k_epi2<<<1184, 256>>>(out, N);
}